// round 14
// baseline (speedup 1.0000x reference)
#include <cuda_runtime.h>
#include <cuda_fp16.h>

// DeformMaxPool2d, R11: R10 (persistent CTAs, fp16 smem scatter, register-
// deferred epilogue) + two-choice bank derandomization of the scatter map.
//
// max() is commutative -> which of output p's 4 slots a source pixel uses is
// free. Slots {4p,4p+1} sit in smem bank (2p)&31, {4p+2,4p+3} in (2p+1)&31:
// each pixel has a 2-bank choice. Each pixel's (iter j, store c, warp w) bin
// is known at build time, so a parallel greedy 2-choice assignment (repair
// kernel) cuts the scatter's expected max bank load ~3.4 -> ~2.2, flipping
// the main kernel from crossbar-bound to DRAM-bound. Races in the greedy only
// change slot positions, never the value set per output -> outputs identical.

#define PLANE_PIX 65536
#define PLANE_OUT 16384
#define THREADS   1024
#define NBINS     2048                 // j(16) * c(4) * warp(32)
#define SMEM_BYTES (PLANE_PIX * 2)     // 128 KB fp16 scatter buffer

__device__ unsigned short g_scatter[PLANE_PIX];   // S[q] = 4*p + pos
__device__ unsigned g_binload[NBINS * 32];        // per-(bin,bank) load counters
__device__ unsigned g_grp[PLANE_OUT];             // lo16: A-attempts, hi16: B-attempts

// Pass 1: initial assignment (gather order) + zero repair state.
__global__ void build_scatter_kernel(const int* __restrict__ gidx)
{
    int p = blockIdx.x * blockDim.x + threadIdx.x;
    if (p >= PLANE_OUT) return;
    int4 g = __ldg(&((const int4*)gidx)[p]);
    unsigned base = (unsigned)(p << 2);
    g_scatter[g.x] = (unsigned short)(base + 0);
    g_scatter[g.y] = (unsigned short)(base + 1);
    g_scatter[g.z] = (unsigned short)(base + 2);
    g_scatter[g.w] = (unsigned short)(base + 3);
    g_grp[p] = 0;
    #pragma unroll
    for (int t = 0; t < 4; t++)
        g_binload[p * 4 + t] = 0;      // 16384*4 = 65536 = NBINS*32
}

// Pass 2: two-choice greedy bank balancing (one thread per source pixel).
__global__ void repair_scatter_kernel()
{
    int q = blockIdx.x * blockDim.x + threadIdx.x;
    if (q >= PLANE_PIX) return;

    unsigned p = (unsigned)g_scatter[q] >> 2;

    // Main-kernel coordinates of pixel q (must mirror the scatter loop).
    int i   = q >> 2;                  // float4 group index
    int c   = q & 3;                   // which store instruction
    int tid = i & (THREADS - 1);
    int j   = i >> 10;                 // iteration
    int w   = tid >> 5;                // warp
    int bin = (((j << 2) | c) << 5) | w;

    unsigned bA = (2u * p) & 31u;      // bank of positions {0,1}
    unsigned bB = (2u * p + 1u) & 31u; // bank of positions {2,3}
    unsigned lA = g_binload[bin * 32 + bA];
    unsigned lB = g_binload[bin * 32 + bB];

    unsigned pos, bank;
    if (lA <= lB) {
        unsigned r = atomicAdd(&g_grp[p], 1u) & 0xffffu;
        if (r < 2u) { pos = r; bank = bA; }
        else { unsigned r2 = (atomicAdd(&g_grp[p], 1u << 16) >> 16) & 0xffffu;
               pos = 2u + r2; bank = bB; }
    } else {
        unsigned r = (atomicAdd(&g_grp[p], 1u << 16) >> 16) & 0xffffu;
        if (r < 2u) { pos = 2u + r; bank = bB; }
        else { unsigned r2 = atomicAdd(&g_grp[p], 1u) & 0xffffu;
               pos = r2; bank = bA; }
    }
    atomicAdd(&g_binload[bin * 32 + bank], 1u);
    g_scatter[q] = (unsigned short)((p << 2) + pos);
}

__global__ __launch_bounds__(THREADS, 1)
void deform_maxpool_r11(const float* __restrict__ x,
                        float*       __restrict__ out,
                        int nplanes)
{
    extern __shared__ __half sy[];               // sy[4p+pos] = fp16(x[src])
    const int tid = threadIdx.x;
    const ushort4* __restrict__ s4 = (const ushort4*)g_scatter;

    __half2 keep[8];                             // previous plane's outputs
    float2* prev_op = nullptr;

    int plane = blockIdx.x;
    // Map chunk for j=0 is plane-invariant; x chunk prefetched per plane.
    ushort4 ps = __ldg(&s4[tid]);
    float4  pv;
    if (plane < nplanes)
        pv = __ldg(&((const float4*)(x + (size_t)plane * PLANE_PIX))[tid]);

    for (; plane < nplanes; plane += gridDim.x) {
        const float4* __restrict__ xp4 =
            (const float4*)(x + (size_t)plane * PLANE_PIX);

        // ---- Phase A: scatter + deferred epilogue of previous plane ----
        #pragma unroll
        for (int j = 0; j < 16; j++) {
            float4  v;
            ushort4 s;
            if (j == 0) { v = pv; s = ps; }
            else {
                int i = tid + j * THREADS;
                v = __ldg(&xp4[i]);
                s = __ldg(&s4[i]);
            }
            __half2 h01 = __floats2half2_rn(v.x, v.y);
            __half2 h23 = __floats2half2_rn(v.z, v.w);
            sy[s.x] = __low2half(h01);
            sy[s.y] = __high2half(h01);
            sy[s.z] = __low2half(h23);
            sy[s.w] = __high2half(h23);
            if (prev_op && (j & 1) == 0) {       // coalesced STG.64 drip
                int jj = j >> 1;
                prev_op[tid + jj * THREADS] = __half22float2(keep[jj]);
            }
        }
        __syncthreads();

        // ---- Phase B: LDS.128 reduce into registers ----
        {
            const uint4* __restrict__ syv = (const uint4*)sy;
            #pragma unroll
            for (int jj = 0; jj < 8; jj++) {
                int p4 = tid + jj * THREADS;
                uint4 w = syv[p4];
                __half2 mA = __hmax2(*(__half2*)&w.x, *(__half2*)&w.y);
                __half2 mB = __hmax2(*(__half2*)&w.z, *(__half2*)&w.w);
                keep[jj] = __halves2half2(
                    __hmax(__low2half(mA), __high2half(mA)),
                    __hmax(__low2half(mB), __high2half(mB)));
            }
        }

        // Prefetch next plane's first x chunk (keeps DRAM pipe primed
        // across the barrier; independent of smem).
        int next = plane + gridDim.x;
        if (next < nplanes)
            pv = __ldg(&((const float4*)(x + (size_t)next * PLANE_PIX))[tid]);

        __syncthreads();                         // sy reuse vs next scatter

        prev_op = (float2*)(out + (size_t)plane * PLANE_OUT);
    }

    // ---- Final epilogue for the last plane this CTA processed ----
    if (prev_op) {
        #pragma unroll
        for (int jj = 0; jj < 8; jj++)
            prev_op[tid + jj * THREADS] = __half22float2(keep[jj]);
    }
}

extern "C" void kernel_launch(void* const* d_in, const int* in_sizes, int n_in,
                              void* d_out, int out_size)
{
    const float* x    = (const float*)d_in[0];
    const int*   gidx = (const int*)d_in[1];
    float*       out  = (float*)d_out;

    const int nplanes = in_sizes[0] / PLANE_PIX;   // 1024

    int dev = 0, sms = 148;
    cudaGetDevice(&dev);
    cudaDeviceGetAttribute(&sms, cudaDevAttrMultiProcessorCount, dev);
    int grid = nplanes < sms ? nplanes : sms;      // persistent: 1 CTA per SM

    cudaFuncSetAttribute(deform_maxpool_r11,
                         cudaFuncAttributeMaxDynamicSharedMemorySize, SMEM_BYTES);

    build_scatter_kernel<<<(PLANE_OUT + 255) / 256, 256>>>(gidx);
    repair_scatter_kernel<<<(PLANE_PIX + 255) / 256, 256>>>();
    deform_maxpool_r11<<<grid, THREADS, SMEM_BYTES>>>(x, out, nplanes);
}